// round 15
// baseline (speedup 1.0000x reference)
#include <cuda_runtime.h>
#include <cuda_bf16.h>

#define NB 16
#define CC 256
#define HWP 4096
#define NELEM (NB*CC*HWP)

typedef unsigned int u32;
typedef unsigned long long u64;

// ---------------- scratch (static device allocations) ----------------
__device__ float g_g1[NELEM];      // g1 in phase 1; reused as y3 (=W3*dw) in phase 2
__device__ float g_XG[NELEM];
__device__ float g_xL[NELEM];

__device__ __align__(256) __nv_bfloat16 g_dwh[NELEM];
__device__ __align__(256) __nv_bfloat16 g_dwl[NELEM];
__device__ __align__(256) __nv_bfloat16 g_xuh[NELEM];
__device__ __align__(256) __nv_bfloat16 g_xul[NELEM];
__device__ __align__(256) __nv_bfloat16 g_w1h[CC*CC];
__device__ __align__(256) __nv_bfloat16 g_w1l[CC*CC];
__device__ __align__(256) __nv_bfloat16 g_w2h[CC*CC];
__device__ __align__(256) __nv_bfloat16 g_w2l[CC*CC];
__device__ __align__(256) __nv_bfloat16 g_w3h[CC*CC];
__device__ __align__(256) __nv_bfloat16 g_w3l[CC*CC];
__device__ __align__(256) __nv_bfloat16 g_w4h[CC*CC];
__device__ __align__(256) __nv_bfloat16 g_w4l[CC*CC];

__device__ float g_sum[NB*CC];
__device__ float g_sumsq[NB*CC];
__device__ float g_mean[NB*CC];
__device__ float g_cagate[NB*CC];
__device__ float g_sumxlow[NB*CC];
__device__ float g_gate[NB*CC];
__device__ float g_bninv[CC];
__device__ float g_bnsh[CC];
__device__ float g_gmu[NB*16];
__device__ float g_grstd[NB*16];
__device__ float g_s4g[NB*HWP];
__device__ float g_xh[NB*CC*64];
__device__ float g_xw[NB*CC*64];
__device__ float g_sh[NB*CC*64];
__device__ float g_sw[NB*CC*64];

__device__ __forceinline__ float sigm(float x){ return 1.0f/(1.0f+expf(-x)); }

// ---------------- K0a/b/c: zero accumulators + weight conversions ----------------
__global__ void k0a_zero()
{
    int i = blockIdx.x*256 + threadIdx.x;
    if (i < NB*CC){ g_sum[i]=0.f; g_sumsq[i]=0.f; }
    if (i < NB*HWP) g_s4g[i]=0.f;
}
__global__ void k0b_cvt(const float* __restrict__ w1, const float* __restrict__ w2)
{
    int i = blockIdx.x*256 + threadIdx.x;
    float a; __nv_bfloat16 h;
    a = w1[i]; h = __float2bfloat16(a);
    g_w1h[i] = h; g_w1l[i] = __float2bfloat16(a - __bfloat162float(h));
    a = w2[i]; h = __float2bfloat16(a);
    g_w2h[i] = h; g_w2l[i] = __float2bfloat16(a - __bfloat162float(h));
}
__global__ void k0c_cvt(const float* __restrict__ w3, const float* __restrict__ w4)
{
    int i = blockIdx.x*256 + threadIdx.x;
    float a; __nv_bfloat16 h;
    a = w3[i]; h = __float2bfloat16(a);
    g_w3h[i] = h; g_w3l[i] = __float2bfloat16(a - __bfloat162float(h));
    a = w4[i]; h = __float2bfloat16(a);
    g_w4h[i] = h; g_w4l[i] = __float2bfloat16(a - __bfloat162float(h));
}

// ================= single-matrix bf16-split tensor-core GEMM core =================
// CTA tile: M=128, N=64, K in 4 chunks of 64. 3 variant passes: hh, lh, hl.

struct GS1 {
    __nv_bfloat16 A[2][128][72];  // [var][o][k]
    __nv_bfloat16 B[2][64][72];   // [var][k][p]
};
#define GS1_BYTES  ((int)sizeof(GS1))
#define GS1D_BYTES (2*GS1_BYTES)

__device__ __forceinline__ u32 smaddr(const void* p){
    return (u32)__cvta_generic_to_shared(p);
}
__device__ __forceinline__ void ldm4(u32* r, const void* p){
    asm volatile("ldmatrix.sync.aligned.m8n8.x4.shared.b16 {%0,%1,%2,%3}, [%4];"
        : "=r"(r[0]),"=r"(r[1]),"=r"(r[2]),"=r"(r[3]) : "r"(smaddr(p)));
}
__device__ __forceinline__ void ldm4t(u32* r, const void* p){
    asm volatile("ldmatrix.sync.aligned.m8n8.x4.trans.shared.b16 {%0,%1,%2,%3}, [%4];"
        : "=r"(r[0]),"=r"(r[1]),"=r"(r[2]),"=r"(r[3]) : "r"(smaddr(p)));
}
__device__ __forceinline__ void mma16816(float* c, const u32* a, const u32* b){
    asm volatile(
        "mma.sync.aligned.m16n8k16.row.col.f32.bf16.bf16.f32 "
        "{%0,%1,%2,%3},{%4,%5,%6,%7},{%8,%9},{%0,%1,%2,%3};"
        : "+f"(c[0]),"+f"(c[1]),"+f"(c[2]),"+f"(c[3])
        : "r"(a[0]),"r"(a[1]),"r"(a[2]),"r"(a[3]), "r"(b[0]),"r"(b[1]));
}

__device__ __forceinline__ unsigned short bfbits(__nv_bfloat16 h){
    return __bfloat16_as_ushort(h);
}
__device__ __forceinline__ u32 cvt2(float f0, float f1, bool lo){
    __nv_bfloat16 h0 = __float2bfloat16(f0);
    __nv_bfloat16 h1 = __float2bfloat16(f1);
    if (lo){
        h0 = __float2bfloat16(f0 - __bfloat162float(h0));
        h1 = __float2bfloat16(f1 - __bfloat162float(h1));
    }
    return ((u32)bfbits(h1) << 16) | (u32)bfbits(h0);
}

__device__ __forceinline__ void cpa16(void* dst, const void* src){
    asm volatile("cp.async.cg.shared.global [%0], [%1], 16;"
                 :: "r"(smaddr(dst)), "l"(src));
}
__device__ __forceinline__ void cpa_commit(){ asm volatile("cp.async.commit_group;"); }
__device__ __forceinline__ void cpa_wait0(){ asm volatile("cp.async.wait_group 0;"); }

// stage A chunk [128 o][64 k] (plain copy)
__device__ __forceinline__ void stage_a1(GS1* S, int var,
    const __nv_bfloat16* __restrict__ w, int oBase, int ks, int tid)
{
    int o  = tid >> 1;
    int kh = (tid & 1) * 32;
    const uint4* s = (const uint4*)(w + (size_t)(oBase+o)*CC + ks + kh);
    uint4* d = (uint4*)&S->A[var][o][kh];
    #pragma unroll
    for (int j=0;j<4;j++) d[j] = s[j];
}

// stage A chunk via cp.async (k5)
__device__ __forceinline__ void stage_a1_ca(GS1* S, int var,
    const __nv_bfloat16* __restrict__ w, int oBase, int ks, int tid)
{
    int o  = tid >> 1;
    int kh = (tid & 1) * 32;
    const uint4* s = (const uint4*)(w + (size_t)(oBase+o)*CC + ks + kh);
    uint4* d = (uint4*)&S->A[var][o][kh];
    #pragma unroll
    for (int j=0;j<4;j++) cpa16(d+j, s+j);
}

// stage B chunk [64 k][64 p] with inline fp32 -> bf16 hi/lo conversion (k1)
__device__ __forceinline__ void stage_b_cvt1(GS1* S,
    const float* __restrict__ x, int pBase, int ks, int tid)
{
    int k   = tid >> 2;
    int seg = tid & 3;
    const float* gp = x + (size_t)(ks+k)*HWP + pBase + seg*16;
    u32* dh = (u32*)&S->B[0][k][seg*16];
    u32* dl = (u32*)&S->B[1][k][seg*16];
    #pragma unroll
    for (int j=0;j<4;j++){
        float4 q = *(const float4*)(gp + j*4);
        dh[2*j+0] = cvt2(q.x, q.y, false);
        dh[2*j+1] = cvt2(q.z, q.w, false);
        dl[2*j+0] = cvt2(q.x, q.y, true);
        dl[2*j+1] = cvt2(q.z, q.w, true);
    }
}

// stage B chunk via cp.async from pre-converted bf16 buffers (k5)
__device__ __forceinline__ void stage_b_copy1_ca(GS1* S, int var,
    const __nv_bfloat16* __restrict__ b, int pBase, int ks, int tid)
{
    int k   = tid >> 2;
    int seg = tid & 3;
    const uint4* s = (const uint4*)(b + (size_t)(ks+k)*HWP + pBase + seg*16);
    uint4* d = (uint4*)&S->B[var][k][seg*16];
    cpa16(d+0, s+0);
    cpa16(d+1, s+1);
}

// one variant pass over a staged chunk: A variant va x B variant vb
__device__ __forceinline__ void mma1_v(GS1* S,
    float acc[2][4][4], int va, int vb, int wm, int wn, int l)
{
    #pragma unroll
    for (int kk=0; kk<4; kk++){
        u32 a[2][4];
        #pragma unroll
        for (int mt=0; mt<2; mt++)
            ldm4(a[mt], &S->A[va][wm*32 + mt*16 + (l&15)][kk*16 + ((l>>4)<<3)]);
        u32 b[2][4];
        int kr = kk*16 + (l&7) + ((l>>3)&1)*8;
        #pragma unroll
        for (int nb=0; nb<2; nb++)
            ldm4t(b[nb], &S->B[vb][kr][wn*32 + nb*16 + ((l>>4)<<3)]);
        #pragma unroll
        for (int mt=0; mt<2; mt++)
            #pragma unroll
            for (int nt=0; nt<4; nt++)
                mma16816(acc[mt][nt], a[mt], &b[nt>>1][(nt&1)*2]);
    }
}

#define GEMM1_MAINLOOP(WH, WL, STAGE_B)                    \
    for (int c=0; c<4; c++){                               \
        int ks = c*64;                                     \
        stage_a1(S, 0, WH, oBase, ks, tid);                \
        stage_a1(S, 1, WL, oBase, ks, tid);                \
        STAGE_B;                                           \
        __syncthreads();                                   \
        mma1_v(S, acc, 0, 0, wm, wn, l);                   \
        mma1_v(S, acc, 1, 0, wm, wn, l);                   \
        mma1_v(S, acc, 0, 1, wm, wn, l);                   \
        __syncthreads();                                   \
    }

// double-buffered full-cp.async mainloop (k5: pure-copy staging)
#define GEMM1_MAINLOOP_DB(WH, WL, B0, B1)                                     \
    {                                                                          \
        stage_a1_ca(&stg[0], 0, WH, oBase, 0, tid);                            \
        stage_a1_ca(&stg[0], 1, WL, oBase, 0, tid);                            \
        stage_b_copy1_ca(&stg[0], 0, B0, pBase, 0, tid);                       \
        stage_b_copy1_ca(&stg[0], 1, B1, pBase, 0, tid);                       \
        cpa_commit(); cpa_wait0(); __syncthreads();                            \
    }                                                                          \
    for (int c=0; c<4; c++){                                                   \
        const int cur = c & 1;                                                 \
        if (c < 3){                                                            \
            int ks = (c+1)*64;                                                 \
            GS1* Sn = &stg[cur^1];                                             \
            stage_a1_ca(Sn, 0, WH, oBase, ks, tid);                            \
            stage_a1_ca(Sn, 1, WL, oBase, ks, tid);                            \
            stage_b_copy1_ca(Sn, 0, B0, pBase, ks, tid);                       \
            stage_b_copy1_ca(Sn, 1, B1, pBase, ks, tid);                       \
            cpa_commit();                                                      \
        }                                                                      \
        GS1* S = &stg[cur];                                                    \
        mma1_v(S, acc, 0, 0, wm, wn, l);                                       \
        mma1_v(S, acc, 1, 0, wm, wn, l);                                       \
        mma1_v(S, acc, 0, 1, wm, wn, l);                                       \
        if (c < 3) cpa_wait0();                                                \
        __syncthreads();                                                       \
    }

// ---------------- K1a: g1 = W1 x1 + b1 ----------------
__global__ __launch_bounds__(256, 2) void k1a_gemm(
    const float* __restrict__ x1, const float* __restrict__ b1)
{
    extern __shared__ char smraw[];
    GS1* S = (GS1*)smraw;

    const int tid = threadIdx.x;
    const int l = tid & 31, w = tid >> 5;
    const int wm = w & 3, wn = w >> 2;
    const int pBase = blockIdx.x * 64;
    const int oBase = blockIdx.y * 128;
    const int n = blockIdx.z;
    const float* Bg = x1 + (size_t)n * CC * HWP;

    float acc[2][4][4];
    #pragma unroll
    for (int mt=0;mt<2;mt++)
        #pragma unroll
        for (int nt=0;nt<4;nt++)
            #pragma unroll
            for (int r=0;r<4;r++) acc[mt][nt][r]=0.f;

    GEMM1_MAINLOOP(g_w1h, g_w1l, stage_b_cvt1(S, Bg, pBase, ks, tid))

    const size_t nb = (size_t)n * CC * HWP;
    #pragma unroll
    for (int mt=0;mt<2;mt++){
        #pragma unroll
        for (int hf=0;hf<2;hf++){
            int o = oBase + wm*32 + mt*16 + (l>>2) + hf*8;
            float bb1 = b1[o];
            #pragma unroll
            for (int nt=0;nt<4;nt++){
                size_t idx = nb + (size_t)o*HWP + pBase + wn*32 + nt*8 + 2*(l&3);
                *(float2*)(g_g1 + idx) =
                    make_float2(acc[mt][nt][hf*2+0] + bb1, acc[mt][nt][hf*2+1] + bb1);
            }
        }
    }
}

// ---------------- K1b: g2 = W2 x2 + b2 ; XG = g1+g2 ; fused reductions ----------------
__global__ __launch_bounds__(256, 2) void k1b_gemm(
    const float* __restrict__ x2, const float* __restrict__ b2,
    const float* __restrict__ w4g)
{
    extern __shared__ char smraw[];
    GS1* S = (GS1*)smraw;
    __shared__ float sSum[128];
    __shared__ float sSq[128];
    __shared__ float sS4[64];

    const int tid = threadIdx.x;
    const int l = tid & 31, w = tid >> 5;
    const int wm = w & 3, wn = w >> 2;
    const int pBase = blockIdx.x * 64;
    const int oBase = blockIdx.y * 128;
    const int n = blockIdx.z;
    const float* Bg = x2 + (size_t)n * CC * HWP;

    if (tid < 128){ sSum[tid] = 0.f; sSq[tid] = 0.f; }
    if (tid < 64) sS4[tid] = 0.f;

    float acc[2][4][4];
    #pragma unroll
    for (int mt=0;mt<2;mt++)
        #pragma unroll
        for (int nt=0;nt<4;nt++)
            #pragma unroll
            for (int r=0;r<4;r++) acc[mt][nt][r]=0.f;

    GEMM1_MAINLOOP(g_w2h, g_w2l, stage_b_cvt1(S, Bg, pBase, ks, tid))

    const size_t nb = (size_t)n * CC * HWP;
    float s4loc[4][2];
    #pragma unroll
    for (int nt=0;nt<4;nt++){ s4loc[nt][0]=0.f; s4loc[nt][1]=0.f; }

    #pragma unroll
    for (int mt=0;mt<2;mt++){
        #pragma unroll
        for (int hf=0;hf<2;hf++){
            int orow = wm*32 + mt*16 + (l>>2) + hf*8;
            int o = oBase + orow;
            float bb2 = b2[o], wg = w4g[o];
            float ss = 0.f, sq = 0.f;
            #pragma unroll
            for (int nt=0;nt<4;nt++){
                size_t idx = nb + (size_t)o*HWP + pBase + wn*32 + nt*8 + 2*(l&3);
                float2 g1v = *(const float2*)(g_g1 + idx);
                float g2x = acc[mt][nt][hf*2+0] + bb2;
                float g2y = acc[mt][nt][hf*2+1] + bb2;
                float xgx = g1v.x + g2x, xgy = g1v.y + g2y;
                *(float2*)(g_XG + idx) = make_float2(xgx, xgy);
                ss += xgx + xgy;
                sq = fmaf(xgx, xgx, sq);
                sq = fmaf(xgy, xgy, sq);
                s4loc[nt][0] = fmaf(wg, xgx, s4loc[nt][0]);
                s4loc[nt][1] = fmaf(wg, xgy, s4loc[nt][1]);
            }
            ss += __shfl_xor_sync(0xffffffffu, ss, 1);
            ss += __shfl_xor_sync(0xffffffffu, ss, 2);
            sq += __shfl_xor_sync(0xffffffffu, sq, 1);
            sq += __shfl_xor_sync(0xffffffffu, sq, 2);
            if ((l & 3) == 0){
                atomicAdd(&sSum[orow], ss);
                atomicAdd(&sSq[orow],  sq);
            }
        }
    }
    #pragma unroll
    for (int nt=0;nt<4;nt++){
        #pragma unroll
        for (int e=0;e<2;e++){
            float v = s4loc[nt][e];
            v += __shfl_xor_sync(0xffffffffu, v, 4);
            v += __shfl_xor_sync(0xffffffffu, v, 8);
            v += __shfl_xor_sync(0xffffffffu, v, 16);
            if (l < 4)
                atomicAdd(&sS4[wn*32 + nt*8 + 2*l + e], v);
        }
    }
    __syncthreads();
    if (tid < 128){
        atomicAdd(&g_sum[n*CC + oBase + tid],   sSum[tid]);
        atomicAdd(&g_sumsq[n*CC + oBase + tid], sSq[tid]);
    }
    if (tid < 64)
        atomicAdd(&g_s4g[(size_t)n*HWP + pBase + tid], sS4[tid]);
}

// ---------------- K5a: y3 = W3 dw (raw) -> g_g1 (reused), double-buffered ----------------
__global__ __launch_bounds__(256, 2) void k5a_gemm()
{
    extern __shared__ char smraw[];
    GS1* stg = (GS1*)smraw;

    const int tid = threadIdx.x;
    const int l = tid & 31, w = tid >> 5;
    const int wm = w & 3, wn = w >> 2;
    const int pBase = blockIdx.x * 64;
    const int oBase = blockIdx.y * 128;
    const int n = blockIdx.z;
    const size_t act = (size_t)n * CC * HWP;
    const __nv_bfloat16* B0 = g_dwh + act;
    const __nv_bfloat16* B1 = g_dwl + act;

    float acc[2][4][4];
    #pragma unroll
    for (int mt=0;mt<2;mt++)
        #pragma unroll
        for (int nt=0;nt<4;nt++)
            #pragma unroll
            for (int r=0;r<4;r++) acc[mt][nt][r]=0.f;

    GEMM1_MAINLOOP_DB(g_w3h, g_w3l, B0, B1)

    const size_t nb = (size_t)n * CC * HWP;
    #pragma unroll
    for (int mt=0;mt<2;mt++){
        #pragma unroll
        for (int hf=0;hf<2;hf++){
            int o = oBase + wm*32 + mt*16 + (l>>2) + hf*8;
            #pragma unroll
            for (int nt=0;nt<4;nt++){
                size_t idx = nb + (size_t)o*HWP + pBase + wn*32 + nt*8 + 2*(l&3);
                *(float2*)(g_g1 + idx) =
                    make_float2(acc[mt][nt][hf*2+0], acc[mt][nt][hf*2+1]);
            }
        }
    }
}

// ---------------- K5b: xL = gate*(y3+b3) + (W4 xup + b4) + base(inline), double-buffered ----------------
__global__ __launch_bounds__(256, 2) void k5b_gemm(
    const float* __restrict__ b3, const float* __restrict__ b4,
    const float* __restrict__ gamma, const float* __restrict__ beta,
    const float* __restrict__ b4g)
{
    extern __shared__ char smraw[];
    GS1* stg = (GS1*)smraw;

    const int tid = threadIdx.x;
    const int l = tid & 31, w = tid >> 5;
    const int wm = w & 3, wn = w >> 2;
    const int pBase = blockIdx.x * 64;
    const int oBase = blockIdx.y * 128;
    const int n = blockIdx.z;
    const size_t act = (size_t)n * CC * HWP;
    const __nv_bfloat16* B0 = g_xuh + act;
    const __nv_bfloat16* B1 = g_xul + act;

    float acc[2][4][4];
    #pragma unroll
    for (int mt=0;mt<2;mt++)
        #pragma unroll
        for (int nt=0;nt<4;nt++)
            #pragma unroll
            for (int r=0;r<4;r++) acc[mt][nt][r]=0.f;

    GEMM1_MAINLOOP_DB(g_w4h, g_w4l, B0, B1)

    const size_t nb = (size_t)n * CC * HWP;
    const float b4s = b4g[0];
    #pragma unroll
    for (int mt=0;mt<2;mt++){
        #pragma unroll
        for (int hf=0;hf<2;hf++){
            int o = oBase + wm*32 + mt*16 + (l>>2) + hf*8;
            float bb3 = b3[o], bb4 = b4[o];
            float gt = g_gate[n*CC + o];
            const int g = o >> 4;
            const float mu = g_gmu[n*16+g], rstd = g_grstd[n*16+g];
            const float gm = gamma[o], bt = beta[o];
            const float cag = g_cagate[n*CC + o];
            #pragma unroll
            for (int nt=0;nt<4;nt++){
                int pcol = pBase + wn*32 + nt*8 + 2*(l&3);
                size_t idx = nb + (size_t)o*HWP + pcol;
                float2 xg = *(const float2*)(g_XG + idx);
                float2 s4 = *(const float2*)(g_s4g + (size_t)n*HWP + pcol);
                float2 y3 = *(const float2*)(g_g1 + idx);
                float Xsx = xg.x * sigm(s4.x + b4s);
                float Xsy = xg.y * sigm(s4.y + b4s);
                float basex = fmaf((Xsx - mu)*rstd, gm, bt) + xg.x*cag;
                float basey = fmaf((Xsy - mu)*rstd, gm, bt) + xg.y*cag;
                float2 outv;
                outv.x = (y3.x + bb3)*gt + (acc[mt][nt][hf*2+0] + bb4) + basex;
                outv.y = (y3.y + bb3)*gt + (acc[mt][nt][hf*2+1] + bb4) + basey;
                *(float2*)(g_xL + idx) = outv;
            }
        }
    }
}

// ---------------- K2: per-(n,c) stats, channel-att conv1d, group mu/std ----------------
__global__ __launch_bounds__(256) void k2_stats(
    const float* __restrict__ bn_g, const float* __restrict__ bn_b,
    const float* __restrict__ bn_rm, const float* __restrict__ bn_rv,
    const float* __restrict__ ca_w)
{
    const int n = blockIdx.x;
    const int c = threadIdx.x;
    __shared__ float sm[CC];
    float mean = g_sum[n*CC+c] * (1.0f/HWP);
    sm[c] = mean;
    g_mean[n*CC+c] = mean;
    if (n == 0){
        float inv = bn_g[c] * rsqrtf(bn_rv[c] + 1e-5f);
        g_bninv[c] = inv;
        g_bnsh[c]  = bn_b[c] - bn_rm[c]*inv;
    }
    __syncthreads();
    float y = 0.f;
    #pragma unroll
    for (int k=0;k<5;k++){
        int cc2 = c + k - 2;
        if (cc2 >= 0 && cc2 < CC) y = fmaf(sm[cc2], ca_w[k], y);
    }
    g_cagate[n*CC+c] = sigm(y);
    if ((c & 15) == 0){
        float s=0.f, q=0.f;
        for (int t=0;t<16;t++){ s += g_sum[n*CC+c+t]; q += g_sumsq[n*CC+c+t]; }
        const float cnt = 16.0f*HWP;
        float mu  = s / cnt;
        float var = (q - cnt*mu*mu) / (cnt - 1.0f);
        var = fmaxf(var, 0.0f);
        float sd = sqrtf(var);
        g_gmu[n*16 + (c>>4)]   = mu;
        g_grstd[n*16 + (c>>4)] = 1.0f/(sd + 1e-10f);
    }
}

// ---------------- K34: masks/x_up + depthwise 3x3, bf16 hi/lo outputs ----------------
__global__ __launch_bounds__(256) void k_lowdw(
    const float* __restrict__ dw_w, const float* __restrict__ dw_b)
{
    const int nc = blockIdx.x;
    const int n = nc >> 8, c = nc & (CC-1);
    const size_t off = (size_t)nc * HWP;
    const float mean = g_mean[nc];
    const float inv = g_bninv[c], shv = g_bnsh[c];

    __shared__ float tile[66*66];
    __shared__ float wred[8];
    const int tid = threadIdx.x;
    const int w0 = tid & 63;
    const int h0 = tid >> 6;   // 0..3

    for (int i = tid; i < 66*66; i += 256) tile[i] = 0.f;
    __syncthreads();

    float lowsum = 0.f;
    #pragma unroll
    for (int r=0;r<16;r++){
        int h = r*4 + h0;
        int p = h*64 + w0;
        float xg  = g_XG[off + p];
        float g1v = g_g1[off + p];
        float g2v = xg - g1v;
        float fu = ((mean >= fmaf(g1v, inv, shv)) ? 1.f : 0.f)
                 + ((mean >= fmaf(g2v, inv, shv)) ? 1.f : 0.f);
        float xl = xg * (2.0f - fu);
        float xu = xg * fu;
        __nv_bfloat16 uh = __float2bfloat16(xu);
        g_xuh[off + p] = uh;
        g_xul[off + p] = __float2bfloat16(xu - __bfloat162float(uh));
        tile[(h+1)*66 + (w0+1)] = xl;
        lowsum += xl;
    }
    #pragma unroll
    for (int d=16; d; d>>=1) lowsum += __shfl_xor_sync(0xffffffffu, lowsum, d);
    if ((tid & 31) == 0) wred[tid >> 5] = lowsum;
    __syncthreads();
    if (tid == 0){
        float s = 0.f;
        #pragma unroll
        for (int i=0;i<8;i++) s += wred[i];
        g_sumxlow[nc] = s;
    }

    float wc[9];
    #pragma unroll
    for (int k=0;k<9;k++) wc[k] = dw_w[c*9+k];
    const float bb = dw_b[c];
    #pragma unroll
    for (int r=0;r<16;r++){
        int h = r*4 + h0;
        float acc = bb;
        #pragma unroll
        for (int i=0;i<3;i++)
            #pragma unroll
            for (int j=0;j<3;j++)
                acc = fmaf(tile[(h+i)*66 + (w0+j)], wc[i*3+j], acc);
        __nv_bfloat16 dh = __float2bfloat16(acc);
        int p = h*64 + w0;
        g_dwh[off+p] = dh;
        g_dwl[off+p] = __float2bfloat16(acc - __bfloat162float(dh));
    }
}

// ---------------- K3.5: gate = softmax(relu(mean(x_low) @ gate_w.T + b)) ----------------
__global__ __launch_bounds__(256) void k_gate(
    const float* __restrict__ gate_w, const float* __restrict__ gate_b)
{
    const int n = blockIdx.x;
    const int o = threadIdx.x;
    __shared__ float mv[CC];
    __shared__ float red[CC];
    mv[o] = g_sumxlow[n*CC+o] * (1.0f/HWP);
    __syncthreads();
    float acc = gate_b[o];
    #pragma unroll 8
    for (int c2=0;c2<CC;c2++) acc = fmaf(mv[c2], gate_w[(size_t)o*CC + c2], acc);
    acc = fmaxf(acc, 0.0f);
    red[o] = acc; __syncthreads();
    for (int s=128; s; s>>=1){ if (o < s) red[o] = fmaxf(red[o], red[o+s]); __syncthreads(); }
    float m = red[0];
    __syncthreads();
    float e = expf(acc - m);
    red[o] = e; __syncthreads();
    for (int s=128; s; s>>=1){ if (o < s) red[o] += red[o+s]; __syncthreads(); }
    g_gate[n*CC+o] = e / red[0];
}

// ---------------- K6: row/col means of xL ----------------
__global__ __launch_bounds__(256) void k6_redux()
{
    const int nc = blockIdx.x;
    const size_t off = (size_t)nc * HWP;
    __shared__ float rsum[64];
    __shared__ float cpart[4][64];
    const int tid = threadIdx.x, l = tid & 31, wp = tid >> 5;
    if (tid < 64) rsum[tid] = 0.f;
    __syncthreads();
    const int w = (wp & 1)*32 + l;
    const int hq = wp >> 1;
    float colacc = 0.f;
    for (int r=0;r<16;r++){
        int h = hq*16 + r;
        float v = g_xL[off + h*64 + w];
        colacc += v;
        float s = v;
        #pragma unroll
        for (int d=16; d; d>>=1) s += __shfl_xor_sync(0xffffffffu, s, d);
        if (l == 0) atomicAdd(&rsum[h], s);
    }
    cpart[hq][w] = colacc;
    __syncthreads();
    if (tid < 64){
        g_xw[(size_t)nc*64 + tid] =
            (cpart[0][tid]+cpart[1][tid]+cpart[2][tid]+cpart[3][tid]) * (1.0f/64.0f);
        g_xh[(size_t)nc*64 + tid] = rsum[tid] * (1.0f/64.0f);
    }
}

// ---------------- K7: coordinate attention (tiny GEMMs) ----------------
__global__ __launch_bounds__(256) void k7_latt(
    const float* __restrict__ la1_w,
    const float* __restrict__ la_g, const float* __restrict__ la_b,
    const float* __restrict__ la_rm, const float* __restrict__ la_rv,
    const float* __restrict__ fh_w, const float* __restrict__ fw_w)
{
    const int n = blockIdx.x;
    __shared__ float syc[16][128];
    const int tid = threadIdx.x;
    for (int e = tid; e < 16*128; e += 256){
        int m = e >> 7, l = e & 127;
        const float* src = (l < 64) ? (g_xh + (size_t)n*CC*64 + l)
                                    : (g_xw + (size_t)n*CC*64 + (l - 64));
        float acc = 0.f;
        #pragma unroll 8
        for (int c2=0;c2<CC;c2++) acc = fmaf(la1_w[m*CC + c2], src[(size_t)c2*64], acc);
        float inv = la_g[m] * rsqrtf(la_rv[m] + 1e-5f);
        float v = acc*inv + (la_b[m] - la_rm[m]*inv);
        syc[m][l] = fmaxf(v, 0.f);
    }
    __syncthreads();
    const int c = tid;
    for (int pos=0; pos<64; pos++){
        float sh = 0.f, sw = 0.f;
        #pragma unroll
        for (int m=0;m<16;m++){
            sh = fmaf(fh_w[c*16+m], syc[m][pos],      sh);
            sw = fmaf(fw_w[c*16+m], syc[m][64+pos],   sw);
        }
        g_sh[((size_t)n*CC + c)*64 + pos] = sigm(sh);
        g_sw[((size_t)n*CC + c)*64 + pos] = sigm(sw);
    }
}

// ---------------- K8: final out = xL * sh(h) * sw(w) ----------------
__global__ __launch_bounds__(256) void k8_final(float* __restrict__ out)
{
    const int nc = blockIdx.x;
    __shared__ float shv[64], swv[64];
    const int tid = threadIdx.x;
    if (tid < 64) shv[tid] = g_sh[(size_t)nc*64 + tid];
    else if (tid < 128) swv[tid-64] = g_sw[(size_t)nc*64 + (tid-64)];
    __syncthreads();
    const size_t off = (size_t)nc * HWP;
    for (int f = tid; f < 1024; f += 256){
        int p = f*4;
        int h = p >> 6, w = p & 63;
        float4 v = *(const float4*)(g_xL + off + p);
        float a = shv[h];
        v.x *= a*swv[w+0]; v.y *= a*swv[w+1]; v.z *= a*swv[w+2]; v.w *= a*swv[w+3];
        *(float4*)(out + off + p) = v;
    }
}

// ---------------- launch ----------------
extern "C" void kernel_launch(void* const* d_in, const int* in_sizes, int n_in,
                              void* d_out, int out_size)
{
    const float* x1      = (const float*)d_in[0];
    const float* x2      = (const float*)d_in[1];
    const float* conv1_w = (const float*)d_in[2];
    const float* conv1_b = (const float*)d_in[3];
    const float* conv2_w = (const float*)d_in[4];
    const float* conv2_b = (const float*)d_in[5];
    const float* conv3_w = (const float*)d_in[6];
    const float* conv3_b = (const float*)d_in[7];
    const float* conv4_w = (const float*)d_in[8];
    const float* conv4_b = (const float*)d_in[9];
    const float* conv4g_w= (const float*)d_in[10];
    const float* conv4g_b= (const float*)d_in[11];
    const float* bn_g    = (const float*)d_in[12];
    const float* bn_b    = (const float*)d_in[13];
    const float* bn_rm   = (const float*)d_in[14];
    const float* bn_rv   = (const float*)d_in[15];
    const float* gamma   = (const float*)d_in[16];
    const float* beta    = (const float*)d_in[17];
    const float* gate_w  = (const float*)d_in[18];
    const float* gate_b  = (const float*)d_in[19];
    const float* dw_w    = (const float*)d_in[20];
    const float* dw_b    = (const float*)d_in[21];
    // d_in[22], d_in[23]: interact_w / interact_b — dead code (softmax over size-1 axis == 1)
    const float* ca_w    = (const float*)d_in[24];
    const float* la1_w   = (const float*)d_in[25];
    const float* la_g    = (const float*)d_in[26];
    const float* la_b    = (const float*)d_in[27];
    const float* la_rm   = (const float*)d_in[28];
    const float* la_rv   = (const float*)d_in[29];
    const float* fh_w    = (const float*)d_in[30];
    const float* fw_w    = (const float*)d_in[31];
    float* out = (float*)d_out;

    cudaFuncSetAttribute(k1a_gemm, cudaFuncAttributeMaxDynamicSharedMemorySize, GS1_BYTES);
    cudaFuncSetAttribute(k1b_gemm, cudaFuncAttributeMaxDynamicSharedMemorySize, GS1_BYTES);
    cudaFuncSetAttribute(k5a_gemm, cudaFuncAttributeMaxDynamicSharedMemorySize, GS1D_BYTES);
    cudaFuncSetAttribute(k5b_gemm, cudaFuncAttributeMaxDynamicSharedMemorySize, GS1D_BYTES);

    dim3 gg(HWP/64, 2, NB);
    k0a_zero<<<256, 256>>>();
    k0b_cvt<<<256, 256>>>(conv1_w, conv2_w);
    k0c_cvt<<<256, 256>>>(conv3_w, conv4_w);
    k1a_gemm<<<gg, 256, GS1_BYTES>>>(x1, conv1_b);              // 4th launch -> ncu slot
    k1b_gemm<<<gg, 256, GS1_BYTES>>>(x2, conv2_b, conv4g_w);
    k2_stats<<<NB, CC>>>(bn_g, bn_b, bn_rm, bn_rv, ca_w);
    k_lowdw<<<NB*CC, 256>>>(dw_w, dw_b);
    k_gate<<<NB, CC>>>(gate_w, gate_b);
    k5a_gemm<<<gg, 256, GS1D_BYTES>>>();
    k5b_gemm<<<gg, 256, GS1D_BYTES>>>(conv3_b, conv4_b, gamma, beta, conv4g_b);
    k6_redux<<<NB*CC, 256>>>();
    k7_latt<<<NB, CC>>>(la1_w, la_g, la_b, la_rm, la_rv, fh_w, fw_w);
    k8_final<<<NB*CC, 256>>>(out);
}

// round 16
// speedup vs baseline: 1.0486x; 1.0486x over previous
#include <cuda_runtime.h>
#include <cuda_bf16.h>

#define NB 16
#define CC 256
#define HWP 4096
#define NELEM (NB*CC*HWP)

typedef unsigned int u32;
typedef unsigned long long u64;

// ---------------- scratch (static device allocations) ----------------
__device__ float g_g1[NELEM];      // g1 in phase 1; reused as y3 (=W3*dw) in phase 2
__device__ float g_XG[NELEM];
__device__ float g_xL[NELEM];

__device__ __align__(256) __nv_bfloat16 g_dwh[NELEM];
__device__ __align__(256) __nv_bfloat16 g_dwl[NELEM];
__device__ __align__(256) __nv_bfloat16 g_xuh[NELEM];
__device__ __align__(256) __nv_bfloat16 g_xul[NELEM];
__device__ __align__(256) __nv_bfloat16 g_w1h[CC*CC];
__device__ __align__(256) __nv_bfloat16 g_w1l[CC*CC];
__device__ __align__(256) __nv_bfloat16 g_w2h[CC*CC];
__device__ __align__(256) __nv_bfloat16 g_w2l[CC*CC];
__device__ __align__(256) __nv_bfloat16 g_w3h[CC*CC];
__device__ __align__(256) __nv_bfloat16 g_w3l[CC*CC];
__device__ __align__(256) __nv_bfloat16 g_w4h[CC*CC];
__device__ __align__(256) __nv_bfloat16 g_w4l[CC*CC];

__device__ float g_sum[NB*CC];
__device__ float g_sumsq[NB*CC];
__device__ float g_mean[NB*CC];
__device__ float g_cagate[NB*CC];
__device__ float g_sumxlow[NB*CC];
__device__ float g_gate[NB*CC];
__device__ float g_bninv[CC];
__device__ float g_bnsh[CC];
__device__ float g_gmu[NB*16];
__device__ float g_grstd[NB*16];
__device__ float g_s4g[NB*HWP];
__device__ float g_xh[NB*CC*64];
__device__ float g_xw[NB*CC*64];
__device__ float g_sh[NB*CC*64];
__device__ float g_sw[NB*CC*64];

__device__ __forceinline__ float sigm(float x){ return 1.0f/(1.0f+expf(-x)); }

// ---------------- K0a/b/c: zero accumulators + weight conversions ----------------
__global__ void k0a_zero()
{
    int i = blockIdx.x*256 + threadIdx.x;
    if (i < NB*CC){ g_sum[i]=0.f; g_sumsq[i]=0.f; }
    if (i < NB*HWP) g_s4g[i]=0.f;
}
__global__ void k0b_cvt(const float* __restrict__ w1, const float* __restrict__ w2)
{
    int i = blockIdx.x*256 + threadIdx.x;
    float a; __nv_bfloat16 h;
    a = w1[i]; h = __float2bfloat16(a);
    g_w1h[i] = h; g_w1l[i] = __float2bfloat16(a - __bfloat162float(h));
    a = w2[i]; h = __float2bfloat16(a);
    g_w2h[i] = h; g_w2l[i] = __float2bfloat16(a - __bfloat162float(h));
}
__global__ void k0c_cvt(const float* __restrict__ w3, const float* __restrict__ w4)
{
    int i = blockIdx.x*256 + threadIdx.x;
    float a; __nv_bfloat16 h;
    a = w3[i]; h = __float2bfloat16(a);
    g_w3h[i] = h; g_w3l[i] = __float2bfloat16(a - __bfloat162float(h));
    a = w4[i]; h = __float2bfloat16(a);
    g_w4h[i] = h; g_w4l[i] = __float2bfloat16(a - __bfloat162float(h));
}

// ================= single-matrix bf16-split tensor-core GEMM core =================
// CTA tile: M=128, N=64, K in 4 chunks of 64. Fused variant passes per kk:
// load Ah,Bh,Bl -> hh + hl -> reload Al -> lh  (8 LDSM / 24 MMA per kk)

struct GS1 {
    __nv_bfloat16 A[2][128][72];  // [var][o][k]
    __nv_bfloat16 B[2][64][72];   // [var][k][p]
};
#define GS1_BYTES ((int)sizeof(GS1))

__device__ __forceinline__ u32 smaddr(const void* p){
    return (u32)__cvta_generic_to_shared(p);
}
__device__ __forceinline__ void ldm4(u32* r, const void* p){
    asm volatile("ldmatrix.sync.aligned.m8n8.x4.shared.b16 {%0,%1,%2,%3}, [%4];"
        : "=r"(r[0]),"=r"(r[1]),"=r"(r[2]),"=r"(r[3]) : "r"(smaddr(p)));
}
__device__ __forceinline__ void ldm4t(u32* r, const void* p){
    asm volatile("ldmatrix.sync.aligned.m8n8.x4.trans.shared.b16 {%0,%1,%2,%3}, [%4];"
        : "=r"(r[0]),"=r"(r[1]),"=r"(r[2]),"=r"(r[3]) : "r"(smaddr(p)));
}
__device__ __forceinline__ void mma16816(float* c, const u32* a, const u32* b){
    asm volatile(
        "mma.sync.aligned.m16n8k16.row.col.f32.bf16.bf16.f32 "
        "{%0,%1,%2,%3},{%4,%5,%6,%7},{%8,%9},{%0,%1,%2,%3};"
        : "+f"(c[0]),"+f"(c[1]),"+f"(c[2]),"+f"(c[3])
        : "r"(a[0]),"r"(a[1]),"r"(a[2]),"r"(a[3]), "r"(b[0]),"r"(b[1]));
}

__device__ __forceinline__ unsigned short bfbits(__nv_bfloat16 h){
    return __bfloat16_as_ushort(h);
}
__device__ __forceinline__ u32 cvt2(float f0, float f1, bool lo){
    __nv_bfloat16 h0 = __float2bfloat16(f0);
    __nv_bfloat16 h1 = __float2bfloat16(f1);
    if (lo){
        h0 = __float2bfloat16(f0 - __bfloat162float(h0));
        h1 = __float2bfloat16(f1 - __bfloat162float(h1));
    }
    return ((u32)bfbits(h1) << 16) | (u32)bfbits(h0);
}

// stage A chunk [128 o][64 k] (plain copy)
__device__ __forceinline__ void stage_a1(GS1* S, int var,
    const __nv_bfloat16* __restrict__ w, int oBase, int ks, int tid)
{
    int o  = tid >> 1;
    int kh = (tid & 1) * 32;
    const uint4* s = (const uint4*)(w + (size_t)(oBase+o)*CC + ks + kh);
    uint4* d = (uint4*)&S->A[var][o][kh];
    #pragma unroll
    for (int j=0;j<4;j++) d[j] = s[j];
}

// stage B chunk [64 k][64 p] with inline fp32 -> bf16 hi/lo conversion (k1)
__device__ __forceinline__ void stage_b_cvt1(GS1* S,
    const float* __restrict__ x, int pBase, int ks, int tid)
{
    int k   = tid >> 2;
    int seg = tid & 3;
    const float* gp = x + (size_t)(ks+k)*HWP + pBase + seg*16;
    u32* dh = (u32*)&S->B[0][k][seg*16];
    u32* dl = (u32*)&S->B[1][k][seg*16];
    #pragma unroll
    for (int j=0;j<4;j++){
        float4 q = *(const float4*)(gp + j*4);
        dh[2*j+0] = cvt2(q.x, q.y, false);
        dh[2*j+1] = cvt2(q.z, q.w, false);
        dl[2*j+0] = cvt2(q.x, q.y, true);
        dl[2*j+1] = cvt2(q.z, q.w, true);
    }
}

// stage B chunk from pre-converted bf16 buffers (k5)
__device__ __forceinline__ void stage_b_copy1(GS1* S, int var,
    const __nv_bfloat16* __restrict__ b, int pBase, int ks, int tid)
{
    int k   = tid >> 2;
    int seg = tid & 3;
    const uint4* s = (const uint4*)(b + (size_t)(ks+k)*HWP + pBase + seg*16);
    uint4* d = (uint4*)&S->B[var][k][seg*16];
    d[0] = s[0]; d[1] = s[1];
}

// fused 3-variant MMA over a staged chunk (fragment reuse, 8 LDSM / 24 MMA per kk)
__device__ __forceinline__ void mma1_fused(GS1* S,
    float acc[2][4][4], int wm, int wn, int l)
{
    #pragma unroll
    for (int kk=0; kk<4; kk++){
        u32 a[2][4];
        #pragma unroll
        for (int mt=0; mt<2; mt++)
            ldm4(a[mt], &S->A[0][wm*32 + mt*16 + (l&15)][kk*16 + ((l>>4)<<3)]);
        int kr = kk*16 + (l&7) + ((l>>3)&1)*8;
        u32 bh[2][4], bl[2][4];
        #pragma unroll
        for (int nb=0; nb<2; nb++){
            ldm4t(bh[nb], &S->B[0][kr][wn*32 + nb*16 + ((l>>4)<<3)]);
            ldm4t(bl[nb], &S->B[1][kr][wn*32 + nb*16 + ((l>>4)<<3)]);
        }
        // Ah x Bh
        #pragma unroll
        for (int mt=0; mt<2; mt++)
            #pragma unroll
            for (int nt=0; nt<4; nt++)
                mma16816(acc[mt][nt], a[mt], &bh[nt>>1][(nt&1)*2]);
        // Ah x Bl
        #pragma unroll
        for (int mt=0; mt<2; mt++)
            #pragma unroll
            for (int nt=0; nt<4; nt++)
                mma16816(acc[mt][nt], a[mt], &bl[nt>>1][(nt&1)*2]);
        // reload A-lo into same registers
        #pragma unroll
        for (int mt=0; mt<2; mt++)
            ldm4(a[mt], &S->A[1][wm*32 + mt*16 + (l&15)][kk*16 + ((l>>4)<<3)]);
        // Al x Bh
        #pragma unroll
        for (int mt=0; mt<2; mt++)
            #pragma unroll
            for (int nt=0; nt<4; nt++)
                mma16816(acc[mt][nt], a[mt], &bh[nt>>1][(nt&1)*2]);
    }
}

#define GEMM1_MAINLOOP(WH, WL, STAGE_B)                    \
    for (int c=0; c<4; c++){                               \
        int ks = c*64;                                     \
        stage_a1(S, 0, WH, oBase, ks, tid);                \
        stage_a1(S, 1, WL, oBase, ks, tid);                \
        STAGE_B;                                           \
        __syncthreads();                                   \
        mma1_fused(S, acc, wm, wn, l);                     \
        __syncthreads();                                   \
    }

// ---------------- K1a: g1 = W1 x1 + b1 ----------------
__global__ __launch_bounds__(256, 2) void k1a_gemm(
    const float* __restrict__ x1, const float* __restrict__ b1)
{
    extern __shared__ char smraw[];
    GS1* S = (GS1*)smraw;

    const int tid = threadIdx.x;
    const int l = tid & 31, w = tid >> 5;
    const int wm = w & 3, wn = w >> 2;
    const int pBase = blockIdx.x * 64;
    const int oBase = blockIdx.y * 128;
    const int n = blockIdx.z;
    const float* Bg = x1 + (size_t)n * CC * HWP;

    float acc[2][4][4];
    #pragma unroll
    for (int mt=0;mt<2;mt++)
        #pragma unroll
        for (int nt=0;nt<4;nt++)
            #pragma unroll
            for (int r=0;r<4;r++) acc[mt][nt][r]=0.f;

    GEMM1_MAINLOOP(g_w1h, g_w1l, stage_b_cvt1(S, Bg, pBase, ks, tid))

    const size_t nb = (size_t)n * CC * HWP;
    #pragma unroll
    for (int mt=0;mt<2;mt++){
        #pragma unroll
        for (int hf=0;hf<2;hf++){
            int o = oBase + wm*32 + mt*16 + (l>>2) + hf*8;
            float bb1 = b1[o];
            #pragma unroll
            for (int nt=0;nt<4;nt++){
                size_t idx = nb + (size_t)o*HWP + pBase + wn*32 + nt*8 + 2*(l&3);
                *(float2*)(g_g1 + idx) =
                    make_float2(acc[mt][nt][hf*2+0] + bb1, acc[mt][nt][hf*2+1] + bb1);
            }
        }
    }
}

// ---------------- K1b: g2 = W2 x2 + b2 ; XG = g1+g2 ; fused reductions ----------------
__global__ __launch_bounds__(256, 2) void k1b_gemm(
    const float* __restrict__ x2, const float* __restrict__ b2,
    const float* __restrict__ w4g)
{
    extern __shared__ char smraw[];
    GS1* S = (GS1*)smraw;
    __shared__ float sSum[128];
    __shared__ float sSq[128];
    __shared__ float sS4[64];

    const int tid = threadIdx.x;
    const int l = tid & 31, w = tid >> 5;
    const int wm = w & 3, wn = w >> 2;
    const int pBase = blockIdx.x * 64;
    const int oBase = blockIdx.y * 128;
    const int n = blockIdx.z;
    const float* Bg = x2 + (size_t)n * CC * HWP;

    if (tid < 128){ sSum[tid] = 0.f; sSq[tid] = 0.f; }
    if (tid < 64) sS4[tid] = 0.f;

    float acc[2][4][4];
    #pragma unroll
    for (int mt=0;mt<2;mt++)
        #pragma unroll
        for (int nt=0;nt<4;nt++)
            #pragma unroll
            for (int r=0;r<4;r++) acc[mt][nt][r]=0.f;

    GEMM1_MAINLOOP(g_w2h, g_w2l, stage_b_cvt1(S, Bg, pBase, ks, tid))

    const size_t nb = (size_t)n * CC * HWP;
    float s4loc[4][2];
    #pragma unroll
    for (int nt=0;nt<4;nt++){ s4loc[nt][0]=0.f; s4loc[nt][1]=0.f; }

    #pragma unroll
    for (int mt=0;mt<2;mt++){
        #pragma unroll
        for (int hf=0;hf<2;hf++){
            int orow = wm*32 + mt*16 + (l>>2) + hf*8;
            int o = oBase + orow;
            float bb2 = b2[o], wg = w4g[o];
            float ss = 0.f, sq = 0.f;
            #pragma unroll
            for (int nt=0;nt<4;nt++){
                size_t idx = nb + (size_t)o*HWP + pBase + wn*32 + nt*8 + 2*(l&3);
                float2 g1v = *(const float2*)(g_g1 + idx);
                float g2x = acc[mt][nt][hf*2+0] + bb2;
                float g2y = acc[mt][nt][hf*2+1] + bb2;
                float xgx = g1v.x + g2x, xgy = g1v.y + g2y;
                *(float2*)(g_XG + idx) = make_float2(xgx, xgy);
                ss += xgx + xgy;
                sq = fmaf(xgx, xgx, sq);
                sq = fmaf(xgy, xgy, sq);
                s4loc[nt][0] = fmaf(wg, xgx, s4loc[nt][0]);
                s4loc[nt][1] = fmaf(wg, xgy, s4loc[nt][1]);
            }
            ss += __shfl_xor_sync(0xffffffffu, ss, 1);
            ss += __shfl_xor_sync(0xffffffffu, ss, 2);
            sq += __shfl_xor_sync(0xffffffffu, sq, 1);
            sq += __shfl_xor_sync(0xffffffffu, sq, 2);
            if ((l & 3) == 0){
                atomicAdd(&sSum[orow], ss);
                atomicAdd(&sSq[orow],  sq);
            }
        }
    }
    #pragma unroll
    for (int nt=0;nt<4;nt++){
        #pragma unroll
        for (int e=0;e<2;e++){
            float v = s4loc[nt][e];
            v += __shfl_xor_sync(0xffffffffu, v, 4);
            v += __shfl_xor_sync(0xffffffffu, v, 8);
            v += __shfl_xor_sync(0xffffffffu, v, 16);
            if (l < 4)
                atomicAdd(&sS4[wn*32 + nt*8 + 2*l + e], v);
        }
    }
    __syncthreads();
    if (tid < 128){
        atomicAdd(&g_sum[n*CC + oBase + tid],   sSum[tid]);
        atomicAdd(&g_sumsq[n*CC + oBase + tid], sSq[tid]);
    }
    if (tid < 64)
        atomicAdd(&g_s4g[(size_t)n*HWP + pBase + tid], sS4[tid]);
}

// ---------------- K5a: y3 = W3 dw (raw, bias applied in k5b) -> g_g1 (reused) ----------------
__global__ __launch_bounds__(256, 2) void k5a_gemm()
{
    extern __shared__ char smraw[];
    GS1* S = (GS1*)smraw;

    const int tid = threadIdx.x;
    const int l = tid & 31, w = tid >> 5;
    const int wm = w & 3, wn = w >> 2;
    const int pBase = blockIdx.x * 64;
    const int oBase = blockIdx.y * 128;
    const int n = blockIdx.z;
    const size_t act = (size_t)n * CC * HWP;

    float acc[2][4][4];
    #pragma unroll
    for (int mt=0;mt<2;mt++)
        #pragma unroll
        for (int nt=0;nt<4;nt++)
            #pragma unroll
            for (int r=0;r<4;r++) acc[mt][nt][r]=0.f;

    GEMM1_MAINLOOP(g_w3h, g_w3l,
        { stage_b_copy1(S, 0, g_dwh + act, pBase, ks, tid);
          stage_b_copy1(S, 1, g_dwl + act, pBase, ks, tid); })

    const size_t nb = (size_t)n * CC * HWP;
    #pragma unroll
    for (int mt=0;mt<2;mt++){
        #pragma unroll
        for (int hf=0;hf<2;hf++){
            int o = oBase + wm*32 + mt*16 + (l>>2) + hf*8;
            #pragma unroll
            for (int nt=0;nt<4;nt++){
                size_t idx = nb + (size_t)o*HWP + pBase + wn*32 + nt*8 + 2*(l&3);
                *(float2*)(g_g1 + idx) =
                    make_float2(acc[mt][nt][hf*2+0], acc[mt][nt][hf*2+1]);
            }
        }
    }
}

// ---------------- K5b: xL = gate*(y3+b3) + (W4 xup + b4) + base(inline) ----------------
__global__ __launch_bounds__(256, 2) void k5b_gemm(
    const float* __restrict__ b3, const float* __restrict__ b4,
    const float* __restrict__ gamma, const float* __restrict__ beta,
    const float* __restrict__ b4g)
{
    extern __shared__ char smraw[];
    GS1* S = (GS1*)smraw;

    const int tid = threadIdx.x;
    const int l = tid & 31, w = tid >> 5;
    const int wm = w & 3, wn = w >> 2;
    const int pBase = blockIdx.x * 64;
    const int oBase = blockIdx.y * 128;
    const int n = blockIdx.z;
    const size_t act = (size_t)n * CC * HWP;

    float acc[2][4][4];
    #pragma unroll
    for (int mt=0;mt<2;mt++)
        #pragma unroll
        for (int nt=0;nt<4;nt++)
            #pragma unroll
            for (int r=0;r<4;r++) acc[mt][nt][r]=0.f;

    GEMM1_MAINLOOP(g_w4h, g_w4l,
        { stage_b_copy1(S, 0, g_xuh + act, pBase, ks, tid);
          stage_b_copy1(S, 1, g_xul + act, pBase, ks, tid); })

    const size_t nb = (size_t)n * CC * HWP;
    const float b4s = b4g[0];
    #pragma unroll
    for (int mt=0;mt<2;mt++){
        #pragma unroll
        for (int hf=0;hf<2;hf++){
            int o = oBase + wm*32 + mt*16 + (l>>2) + hf*8;
            float bb3 = b3[o], bb4 = b4[o];
            float gt = g_gate[n*CC + o];
            const int g = o >> 4;
            const float mu = g_gmu[n*16+g], rstd = g_grstd[n*16+g];
            const float gm = gamma[o], bt = beta[o];
            const float cag = g_cagate[n*CC + o];
            #pragma unroll
            for (int nt=0;nt<4;nt++){
                int pcol = pBase + wn*32 + nt*8 + 2*(l&3);
                size_t idx = nb + (size_t)o*HWP + pcol;
                float2 xg = *(const float2*)(g_XG + idx);
                float2 s4 = *(const float2*)(g_s4g + (size_t)n*HWP + pcol);
                float2 y3 = *(const float2*)(g_g1 + idx);
                float Xsx = xg.x * sigm(s4.x + b4s);
                float Xsy = xg.y * sigm(s4.y + b4s);
                float basex = fmaf((Xsx - mu)*rstd, gm, bt) + xg.x*cag;
                float basey = fmaf((Xsy - mu)*rstd, gm, bt) + xg.y*cag;
                float2 outv;
                outv.x = (y3.x + bb3)*gt + (acc[mt][nt][hf*2+0] + bb4) + basex;
                outv.y = (y3.y + bb3)*gt + (acc[mt][nt][hf*2+1] + bb4) + basey;
                *(float2*)(g_xL + idx) = outv;
            }
        }
    }
}

// ---------------- K2: per-(n,c) stats, channel-att conv1d, group mu/std ----------------
__global__ __launch_bounds__(256) void k2_stats(
    const float* __restrict__ bn_g, const float* __restrict__ bn_b,
    const float* __restrict__ bn_rm, const float* __restrict__ bn_rv,
    const float* __restrict__ ca_w)
{
    const int n = blockIdx.x;
    const int c = threadIdx.x;
    __shared__ float sm[CC];
    float mean = g_sum[n*CC+c] * (1.0f/HWP);
    sm[c] = mean;
    g_mean[n*CC+c] = mean;
    if (n == 0){
        float inv = bn_g[c] * rsqrtf(bn_rv[c] + 1e-5f);
        g_bninv[c] = inv;
        g_bnsh[c]  = bn_b[c] - bn_rm[c]*inv;
    }
    __syncthreads();
    float y = 0.f;
    #pragma unroll
    for (int k=0;k<5;k++){
        int cc2 = c + k - 2;
        if (cc2 >= 0 && cc2 < CC) y = fmaf(sm[cc2], ca_w[k], y);
    }
    g_cagate[n*CC+c] = sigm(y);
    if ((c & 15) == 0){
        float s=0.f, q=0.f;
        for (int t=0;t<16;t++){ s += g_sum[n*CC+c+t]; q += g_sumsq[n*CC+c+t]; }
        const float cnt = 16.0f*HWP;
        float mu  = s / cnt;
        float var = (q - cnt*mu*mu) / (cnt - 1.0f);
        var = fmaxf(var, 0.0f);
        float sd = sqrtf(var);
        g_gmu[n*16 + (c>>4)]   = mu;
        g_grstd[n*16 + (c>>4)] = 1.0f/(sd + 1e-10f);
    }
}

// ---------------- K34: masks/x_up + depthwise 3x3, bf16 hi/lo outputs ----------------
__global__ __launch_bounds__(256) void k_lowdw(
    const float* __restrict__ dw_w, const float* __restrict__ dw_b)
{
    const int nc = blockIdx.x;
    const int n = nc >> 8, c = nc & (CC-1);
    const size_t off = (size_t)nc * HWP;
    const float mean = g_mean[nc];
    const float inv = g_bninv[c], shv = g_bnsh[c];

    __shared__ float tile[66*66];
    __shared__ float wred[8];
    const int tid = threadIdx.x;
    const int w0 = tid & 63;
    const int h0 = tid >> 6;   // 0..3

    for (int i = tid; i < 66*66; i += 256) tile[i] = 0.f;
    __syncthreads();

    float lowsum = 0.f;
    #pragma unroll
    for (int r=0;r<16;r++){
        int h = r*4 + h0;
        int p = h*64 + w0;
        float xg  = g_XG[off + p];
        float g1v = g_g1[off + p];
        float g2v = xg - g1v;
        float fu = ((mean >= fmaf(g1v, inv, shv)) ? 1.f : 0.f)
                 + ((mean >= fmaf(g2v, inv, shv)) ? 1.f : 0.f);
        float xl = xg * (2.0f - fu);
        float xu = xg * fu;
        __nv_bfloat16 uh = __float2bfloat16(xu);
        g_xuh[off + p] = uh;
        g_xul[off + p] = __float2bfloat16(xu - __bfloat162float(uh));
        tile[(h+1)*66 + (w0+1)] = xl;
        lowsum += xl;
    }
    #pragma unroll
    for (int d=16; d; d>>=1) lowsum += __shfl_xor_sync(0xffffffffu, lowsum, d);
    if ((tid & 31) == 0) wred[tid >> 5] = lowsum;
    __syncthreads();
    if (tid == 0){
        float s = 0.f;
        #pragma unroll
        for (int i=0;i<8;i++) s += wred[i];
        g_sumxlow[nc] = s;
    }

    float wc[9];
    #pragma unroll
    for (int k=0;k<9;k++) wc[k] = dw_w[c*9+k];
    const float bb = dw_b[c];
    #pragma unroll
    for (int r=0;r<16;r++){
        int h = r*4 + h0;
        float acc = bb;
        #pragma unroll
        for (int i=0;i<3;i++)
            #pragma unroll
            for (int j=0;j<3;j++)
                acc = fmaf(tile[(h+i)*66 + (w0+j)], wc[i*3+j], acc);
        __nv_bfloat16 dh = __float2bfloat16(acc);
        int p = h*64 + w0;
        g_dwh[off+p] = dh;
        g_dwl[off+p] = __float2bfloat16(acc - __bfloat162float(dh));
    }
}

// ---------------- K3.5: gate = softmax(relu(mean(x_low) @ gate_w.T + b)) ----------------
__global__ __launch_bounds__(256) void k_gate(
    const float* __restrict__ gate_w, const float* __restrict__ gate_b)
{
    const int n = blockIdx.x;
    const int o = threadIdx.x;
    __shared__ float mv[CC];
    __shared__ float red[CC];
    mv[o] = g_sumxlow[n*CC+o] * (1.0f/HWP);
    __syncthreads();
    float acc = gate_b[o];
    #pragma unroll 8
    for (int c2=0;c2<CC;c2++) acc = fmaf(mv[c2], gate_w[(size_t)o*CC + c2], acc);
    acc = fmaxf(acc, 0.0f);
    red[o] = acc; __syncthreads();
    for (int s=128; s; s>>=1){ if (o < s) red[o] = fmaxf(red[o], red[o+s]); __syncthreads(); }
    float m = red[0];
    __syncthreads();
    float e = expf(acc - m);
    red[o] = e; __syncthreads();
    for (int s=128; s; s>>=1){ if (o < s) red[o] += red[o+s]; __syncthreads(); }
    g_gate[n*CC+o] = e / red[0];
}

// ---------------- K6: row/col means of xL ----------------
__global__ __launch_bounds__(256) void k6_redux()
{
    const int nc = blockIdx.x;
    const size_t off = (size_t)nc * HWP;
    __shared__ float rsum[64];
    __shared__ float cpart[4][64];
    const int tid = threadIdx.x, l = tid & 31, wp = tid >> 5;
    if (tid < 64) rsum[tid] = 0.f;
    __syncthreads();
    const int w = (wp & 1)*32 + l;
    const int hq = wp >> 1;
    float colacc = 0.f;
    for (int r=0;r<16;r++){
        int h = hq*16 + r;
        float v = g_xL[off + h*64 + w];
        colacc += v;
        float s = v;
        #pragma unroll
        for (int d=16; d; d>>=1) s += __shfl_xor_sync(0xffffffffu, s, d);
        if (l == 0) atomicAdd(&rsum[h], s);
    }
    cpart[hq][w] = colacc;
    __syncthreads();
    if (tid < 64){
        g_xw[(size_t)nc*64 + tid] =
            (cpart[0][tid]+cpart[1][tid]+cpart[2][tid]+cpart[3][tid]) * (1.0f/64.0f);
        g_xh[(size_t)nc*64 + tid] = rsum[tid] * (1.0f/64.0f);
    }
}

// ---------------- K7: coordinate attention (tiny GEMMs) ----------------
__global__ __launch_bounds__(256) void k7_latt(
    const float* __restrict__ la1_w,
    const float* __restrict__ la_g, const float* __restrict__ la_b,
    const float* __restrict__ la_rm, const float* __restrict__ la_rv,
    const float* __restrict__ fh_w, const float* __restrict__ fw_w)
{
    const int n = blockIdx.x;
    __shared__ float syc[16][128];
    const int tid = threadIdx.x;
    for (int e = tid; e < 16*128; e += 256){
        int m = e >> 7, l = e & 127;
        const float* src = (l < 64) ? (g_xh + (size_t)n*CC*64 + l)
                                    : (g_xw + (size_t)n*CC*64 + (l - 64));
        float acc = 0.f;
        #pragma unroll 8
        for (int c2=0;c2<CC;c2++) acc = fmaf(la1_w[m*CC + c2], src[(size_t)c2*64], acc);
        float inv = la_g[m] * rsqrtf(la_rv[m] + 1e-5f);
        float v = acc*inv + (la_b[m] - la_rm[m]*inv);
        syc[m][l] = fmaxf(v, 0.f);
    }
    __syncthreads();
    const int c = tid;
    for (int pos=0; pos<64; pos++){
        float sh = 0.f, sw = 0.f;
        #pragma unroll
        for (int m=0;m<16;m++){
            sh = fmaf(fh_w[c*16+m], syc[m][pos],      sh);
            sw = fmaf(fw_w[c*16+m], syc[m][64+pos],   sw);
        }
        g_sh[((size_t)n*CC + c)*64 + pos] = sigm(sh);
        g_sw[((size_t)n*CC + c)*64 + pos] = sigm(sw);
    }
}

// ---------------- K8: final out = xL * sh(h) * sw(w) ----------------
__global__ __launch_bounds__(256) void k8_final(float* __restrict__ out)
{
    const int nc = blockIdx.x;
    __shared__ float shv[64], swv[64];
    const int tid = threadIdx.x;
    if (tid < 64) shv[tid] = g_sh[(size_t)nc*64 + tid];
    else if (tid < 128) swv[tid-64] = g_sw[(size_t)nc*64 + (tid-64)];
    __syncthreads();
    const size_t off = (size_t)nc * HWP;
    for (int f = tid; f < 1024; f += 256){
        int p = f*4;
        int h = p >> 6, w = p & 63;
        float4 v = *(const float4*)(g_xL + off + p);
        float a = shv[h];
        v.x *= a*swv[w+0]; v.y *= a*swv[w+1]; v.z *= a*swv[w+2]; v.w *= a*swv[w+3];
        *(float4*)(out + off + p) = v;
    }
}

// ---------------- launch ----------------
extern "C" void kernel_launch(void* const* d_in, const int* in_sizes, int n_in,
                              void* d_out, int out_size)
{
    const float* x1      = (const float*)d_in[0];
    const float* x2      = (const float*)d_in[1];
    const float* conv1_w = (const float*)d_in[2];
    const float* conv1_b = (const float*)d_in[3];
    const float* conv2_w = (const float*)d_in[4];
    const float* conv2_b = (const float*)d_in[5];
    const float* conv3_w = (const float*)d_in[6];
    const float* conv3_b = (const float*)d_in[7];
    const float* conv4_w = (const float*)d_in[8];
    const float* conv4_b = (const float*)d_in[9];
    const float* conv4g_w= (const float*)d_in[10];
    const float* conv4g_b= (const float*)d_in[11];
    const float* bn_g    = (const float*)d_in[12];
    const float* bn_b    = (const float*)d_in[13];
    const float* bn_rm   = (const float*)d_in[14];
    const float* bn_rv   = (const float*)d_in[15];
    const float* gamma   = (const float*)d_in[16];
    const float* beta    = (const float*)d_in[17];
    const float* gate_w  = (const float*)d_in[18];
    const float* gate_b  = (const float*)d_in[19];
    const float* dw_w    = (const float*)d_in[20];
    const float* dw_b    = (const float*)d_in[21];
    // d_in[22], d_in[23]: interact_w / interact_b — dead code (softmax over size-1 axis == 1)
    const float* ca_w    = (const float*)d_in[24];
    const float* la1_w   = (const float*)d_in[25];
    const float* la_g    = (const float*)d_in[26];
    const float* la_b    = (const float*)d_in[27];
    const float* la_rm   = (const float*)d_in[28];
    const float* la_rv   = (const float*)d_in[29];
    const float* fh_w    = (const float*)d_in[30];
    const float* fw_w    = (const float*)d_in[31];
    float* out = (float*)d_out;

    cudaFuncSetAttribute(k1a_gemm, cudaFuncAttributeMaxDynamicSharedMemorySize, GS1_BYTES);
    cudaFuncSetAttribute(k1b_gemm, cudaFuncAttributeMaxDynamicSharedMemorySize, GS1_BYTES);
    cudaFuncSetAttribute(k5a_gemm, cudaFuncAttributeMaxDynamicSharedMemorySize, GS1_BYTES);
    cudaFuncSetAttribute(k5b_gemm, cudaFuncAttributeMaxDynamicSharedMemorySize, GS1_BYTES);

    dim3 gg(HWP/64, 2, NB);
    k0a_zero<<<256, 256>>>();
    k0b_cvt<<<256, 256>>>(conv1_w, conv2_w);
    k0c_cvt<<<256, 256>>>(conv3_w, conv4_w);
    k1a_gemm<<<gg, 256, GS1_BYTES>>>(x1, conv1_b);              // 4th launch -> ncu slot
    k1b_gemm<<<gg, 256, GS1_BYTES>>>(x2, conv2_b, conv4g_w);
    k2_stats<<<NB, CC>>>(bn_g, bn_b, bn_rm, bn_rv, ca_w);
    k_lowdw<<<NB*CC, 256>>>(dw_w, dw_b);
    k_gate<<<NB, CC>>>(gate_w, gate_b);
    k5a_gemm<<<gg, 256, GS1_BYTES>>>();
    k5b_gemm<<<gg, 256, GS1_BYTES>>>(conv3_b, conv4_b, gamma, beta, conv4g_b);
    k6_redux<<<NB*CC, 256>>>();
    k7_latt<<<NB, CC>>>(la1_w, la_g, la_b, la_rm, la_rv, fh_w, fw_w);
    k8_final<<<NB*CC, 256>>>(out);
}